// round 14
// baseline (speedup 1.0000x reference)
#include <cuda_runtime.h>

#define NNODES 100000
#define NEDGES 1000000
#define NGRAPHS 1000
#define EMBED 64
#define OUTDIM 128
#define NCONV 3
#define BN_EPS 1e-5f

#define SCAN_BLOCKS 391                       // ceil(NNODES/256); all resident
#define EDGE_PER_BLK ((NEDGES + SCAN_BLOCKS - 1) / SCAN_BLOCKS)   // 2558

typedef unsigned long long u64;

// ---------------- scratch (no allocs allowed) ----------------
// stats MUST be 16B-aligned (float4 loads) -> placed first.
struct alignas(16) ZBuf {     // zeroed via one cudaMemsetAsync each call
    float stats[NCONV * 2 * EMBED];   // offset 0, 1536 B (mult of 16)
    int   deg[NNODES];
    int   cnt1;                // setup barrier 1 (counts done)
    int   cnt2;                // setup barrier 2 arrivals
    int   done2;               // setup barrier 2 flag
};
__device__ ZBuf d_Z;

__device__ float d_h[NNODES * EMBED];      // node features
__device__ float d_t[NNODES * EMBED];      // agg + h (GEMM input)
__device__ float d_y[NNODES * EMBED];      // GEMM output (pre-BN)
__device__ int   d_rowptr[NNODES + 1];
__device__ int   d_cursor[NNODES];
__device__ float d_inv[NNODES];            // 1/max(deg,1)
__device__ int   d_aggr[512];
__device__ int   d_off[512];
__device__ unsigned d_edge[NEDGES];        // packed: (src << 8) | efeat
__device__ float d_gn[NGRAPHS * EMBED];

// ---------------- f32x2 helpers ----------------
__device__ __forceinline__ u64 ffma2(u64 a, u64 b, u64 c) {
    u64 d;
    asm("fma.rn.f32x2 %0, %1, %2, %3;" : "=l"(d) : "l"(a), "l"(b), "l"(c));
    return d;
}
__device__ __forceinline__ u64 pack2(float x) {
    u64 d;
    asm("mov.b64 %0, {%1, %1};" : "=l"(d) : "f"(x));
    return d;
}

// ---------------- fused setup: embed + degree count + scan ----------------
// 391 blocks, all resident: two in-kernel spin barriers are deadlock-free.
__global__ void __launch_bounds__(256) k_setup(const int* __restrict__ nfeat,
                                               const float4* __restrict__ atom_embed,
                                               const int* __restrict__ dst) {
    __shared__ int s[256];
    __shared__ int s2[256];
    __shared__ int sdone;
    int t = threadIdx.x, bid = blockIdx.x;

    // phase A1: embed — thread-per-float4, coalesced (16 iters of 256 lanes)
    {
        int base = bid * 4096;                      // 256 nodes * 16 float4
        #pragma unroll 4
        for (int j = 0; j < 16; j++) {
            int idx = base + j * 256 + t;
            if (idx < NNODES * 16) {
                int n = idx >> 4, c4 = idx & 15;
                ((float4*)d_h)[idx] = atom_embed[nfeat[n] * 16 + c4];
            }
        }
    }
    // phase A2: degree count over this block's edge slice
    {
        int e0 = bid * EDGE_PER_BLK;
        int e1 = e0 + EDGE_PER_BLK; if (e1 > NEDGES) e1 = NEDGES;
        for (int e = e0 + t; e < e1; e += 256)
            atomicAdd(&d_Z.deg[dst[e]], 1);
    }
    // barrier 1: all counts globally visible
    __syncthreads();
    if (t == 0) {
        __threadfence();
        atomicAdd(&d_Z.cnt1, 1);
        while (atomicAdd(&d_Z.cnt1, 0) < SCAN_BLOCKS) __nanosleep(40);
    }
    __syncthreads();

    // phase B: block-local scan + cross-block offsets (second spin barrier)
    int i = bid * 256 + t;
    int v = (i < NNODES) ? __ldcg(&d_Z.deg[i]) : 0;
    s[t] = v;
    __syncthreads();
    #pragma unroll
    for (int off = 1; off < 256; off <<= 1) {
        int u = (t >= off) ? s[t - off] : 0;
        __syncthreads();
        s[t] += u;
        __syncthreads();
    }
    int lexcl = s[t] - v;
    int agg = s[255];
    if (t == 0) {
        d_aggr[bid] = agg;
        __threadfence();
        int old = atomicAdd(&d_Z.cnt2, 1);
        sdone = (old == SCAN_BLOCKS - 1);
    }
    __syncthreads();
    if (sdone) {
        int a0 = (2 * t < SCAN_BLOCKS) ? __ldcg(&d_aggr[2 * t]) : 0;
        int a1 = (2 * t + 1 < SCAN_BLOCKS) ? __ldcg(&d_aggr[2 * t + 1]) : 0;
        s2[t] = a0 + a1;
        __syncthreads();
        #pragma unroll
        for (int off = 1; off < 256; off <<= 1) {
            int u = (t >= off) ? s2[t - off] : 0;
            __syncthreads();
            s2[t] += u;
            __syncthreads();
        }
        int ex = s2[t] - (a0 + a1);
        d_off[2 * t] = ex;
        d_off[2 * t + 1] = ex + a0;
        if (t == 255) d_rowptr[NNODES] = s2[255];
        __threadfence();
        if (t == 0) atomicExch(&d_Z.done2, 1);
    }
    if (t == 0) {
        while (atomicAdd(&d_Z.done2, 0) == 0) __nanosleep(40);
    }
    __syncthreads();
    int boff = __ldcg(&d_off[bid]);
    if (i < NNODES) {
        int r = lexcl + boff;
        d_rowptr[i] = r;
        d_cursor[i] = r;
        d_inv[i] = 1.f / (float)(v > 0 ? v : 1);
    }
}

__global__ void k_fill(const int* __restrict__ src,
                       const int* __restrict__ efeat,
                       const int* __restrict__ dst) {
    int e = blockIdx.x * blockDim.x + threadIdx.x;
    if (e >= NEDGES) return;
    int p = atomicAdd(&d_cursor[dst[e]], 1);
    d_edge[p] = ((unsigned)src[e] << 8) | (unsigned)efeat[e];
}

// ---------------- per-layer kernels ----------------
// warp per node, lane covers 2 channels (float2). 4x-unrolled edge loop with
// byte-offset packed edges. __launch_bounds__(256, 8) pins regs to 32 so all
// 8 blocks fit per SM (measured occupancy sweet spot).
__global__ void __launch_bounds__(256, 8) k_msg(const float* __restrict__ bond) {
    __shared__ __align__(16) float bsh[5 * EMBED];
    int tid = threadIdx.x;
    for (int i = tid; i < 5 * EMBED; i += 256) bsh[i] = bond[i];
    __syncthreads();
    int warp = tid >> 5, lane = tid & 31;
    int node = blockIdx.x * 8 + warp;
    if (node >= NNODES) return;
    int rs = d_rowptr[node], re = d_rowptr[node + 1];
    const char* hb = (const char*)d_h + lane * 8;
    const char* bb = (const char*)bsh + lane * 8;
    float2 a0 = make_float2(0.f, 0.f), a1 = a0, a2 = a0, a3 = a0;
    int e = rs;
    for (; e + 3 < re; e += 4) {
        unsigned p0 = d_edge[e],     p1 = d_edge[e + 1];
        unsigned p2 = d_edge[e + 2], p3 = d_edge[e + 3];
        float2 h0 = *(const float2*)(hb + (p0 & 0xFFFFFF00u));
        float2 h1 = *(const float2*)(hb + (p1 & 0xFFFFFF00u));
        float2 h2 = *(const float2*)(hb + (p2 & 0xFFFFFF00u));
        float2 h3 = *(const float2*)(hb + (p3 & 0xFFFFFF00u));
        float2 b0 = *(const float2*)(bb + ((p0 & 255u) << 8));
        float2 b1 = *(const float2*)(bb + ((p1 & 255u) << 8));
        float2 b2 = *(const float2*)(bb + ((p2 & 255u) << 8));
        float2 b3 = *(const float2*)(bb + ((p3 & 255u) << 8));
        a0.x += fmaxf(b0.x + h0.x, 0.f);  a0.y += fmaxf(b0.y + h0.y, 0.f);
        a1.x += fmaxf(b1.x + h1.x, 0.f);  a1.y += fmaxf(b1.y + h1.y, 0.f);
        a2.x += fmaxf(b2.x + h2.x, 0.f);  a2.y += fmaxf(b2.y + h2.y, 0.f);
        a3.x += fmaxf(b3.x + h3.x, 0.f);  a3.y += fmaxf(b3.y + h3.y, 0.f);
    }
    for (; e < re; e++) {
        unsigned p0 = d_edge[e];
        float2 h0 = *(const float2*)(hb + (p0 & 0xFFFFFF00u));
        float2 b0 = *(const float2*)(bb + ((p0 & 255u) << 8));
        a0.x += fmaxf(b0.x + h0.x, 0.f);  a0.y += fmaxf(b0.y + h0.y, 0.f);
    }
    a0.x += a1.x + a2.x + a3.x;
    a0.y += a1.y + a2.y + a3.y;
    float inv = d_inv[node];
    float2 hn = ((const float2*)(d_h + (size_t)node * EMBED))[lane];
    float2 o;
    o.x = a0.x * inv + hn.x;
    o.y = a0.y * inv + hn.y;
    ((float2*)(d_t + (size_t)node * EMBED))[lane] = o;
}

// GEMM split across BLOCKS by column half: grid = 2*391 blocks.
// Block (nb, half) computes y[nb*256 .. +255][half*32 .. +31] with 16 u64
// accumulators per thread (~48 regs) — 782 blocks -> ~5 blocks/SM resident,
// enough warps to hide LDS latency (R13 failed because grid=391 capped
// residency at 2.6 blocks/SM). Fused stats epilogue covers this block's own
// 256 rows x 32 channels (each (row,channel) counted exactly once grid-wide).
__global__ void __launch_bounds__(256, 5) k_gemm(const float* __restrict__ W,
                                                 const float* __restrict__ b,
                                                 int layer) {
    __shared__ ulonglong2 Ws[EMBED * 8];     // this half's 32 channels (8 KB)
    __shared__ float4 ssum[256], ssq[256];
    int tid = threadIdx.x;
    int nb = blockIdx.x >> 1, half = blockIdx.x & 1;
    for (int i = tid; i < EMBED * 8; i += 256) {
        int k = i >> 3, c8 = i & 7;
        Ws[i] = ((const ulonglong2*)W)[k * 16 + half * 8 + c8];
    }
    __syncthreads();
    int node = nb * 256 + tid;
    if (node < NNODES) {
        const float4* tp = (const float4*)(d_t + (size_t)node * EMBED);
        u64 acc[16];
        const u64* bp = (const u64*)b + half * 16;
        #pragma unroll
        for (int i = 0; i < 16; i++) acc[i] = bp[i];
        #pragma unroll 1
        for (int k4 = 0; k4 < 16; k4++) {
            float4 tv = tp[k4];
            #pragma unroll
            for (int j = 0; j < 4; j++) {
                float tk = (j == 0) ? tv.x : (j == 1) ? tv.y : (j == 2) ? tv.z : tv.w;
                u64 tkk = pack2(tk);
                int k = k4 * 4 + j;
                #pragma unroll
                for (int c8 = 0; c8 < 8; c8++) {
                    ulonglong2 w = Ws[k * 8 + c8];
                    acc[2 * c8]     = ffma2(tkk, w.x, acc[2 * c8]);
                    acc[2 * c8 + 1] = ffma2(tkk, w.y, acc[2 * c8 + 1]);
                }
            }
        }
        ulonglong2* yp = (ulonglong2*)(d_y + (size_t)node * EMBED) + half * 8;
        #pragma unroll
        for (int i = 0; i < 8; i++)
            yp[i] = make_ulonglong2(acc[2 * i], acc[2 * i + 1]);
    }
    __syncthreads();   // this block's y channels visible (cta scope)
    // stats: this block's 256 rows x its 8 float4-channels
    int c = tid & 7, grp = tid >> 3;       // 32 row-groups x 8 channels
    int base = nb * 256;
    float4 sum = make_float4(0.f, 0.f, 0.f, 0.f), sq = sum;
    for (int r = grp; r < 256; r += 32) {
        int row = base + r;
        if (row >= NNODES) break;
        float4 v = ((const float4*)d_y)[row * 16 + half * 8 + c];
        sum.x += v.x; sum.y += v.y; sum.z += v.z; sum.w += v.w;
        sq.x += v.x * v.x; sq.y += v.y * v.y; sq.z += v.z * v.z; sq.w += v.w * v.w;
    }
    ssum[tid] = sum; ssq[tid] = sq;
    __syncthreads();
    if (grp == 0) {
        #pragma unroll 4
        for (int g = 1; g < 32; g++) {
            float4 a = ssum[g * 8 + c], q = ssq[g * 8 + c];
            sum.x += a.x; sum.y += a.y; sum.z += a.z; sum.w += a.w;
            sq.x += q.x; sq.y += q.y; sq.z += q.z; sq.w += q.w;
        }
        int c4 = half * 8 + c;
        float* st = d_Z.stats + layer * 128;
        atomicAdd(&st[c4 * 4 + 0], sum.x);
        atomicAdd(&st[c4 * 4 + 1], sum.y);
        atomicAdd(&st[c4 * 4 + 2], sum.z);
        atomicAdd(&st[c4 * 4 + 3], sum.w);
        atomicAdd(&st[64 + c4 * 4 + 0], sq.x);
        atomicAdd(&st[64 + c4 * 4 + 1], sq.y);
        atomicAdd(&st[64 + c4 * 4 + 2], sq.z);
        atomicAdd(&st[64 + c4 * 4 + 3], sq.w);
    }
}

// normalize + gamma/beta + relu + residual (h += act), float4 wide (layers 0,1)
__global__ void k_bn(int layer, const float* __restrict__ gamma,
                     const float* __restrict__ beta) {
    int i = blockIdx.x * blockDim.x + threadIdx.x;   // float4 index
    if (i >= NNODES * 16) return;
    int c4 = i & 15;
    const float* st = d_Z.stats + layer * 128;
    const float invN = 1.f / (float)NNODES;
    float4 s1 = ((const float4*)st)[c4];
    float4 s2 = ((const float4*)(st + 64))[c4];
    float4 g  = ((const float4*)gamma)[c4];
    float4 be = ((const float4*)beta)[c4];
    float4 y  = ((const float4*)d_y)[i];
    float4 h  = ((const float4*)d_h)[i];
    float mu, var, rs, v;
    #define BN1(X) \
        mu = s1.X * invN; var = s2.X * invN - mu * mu; \
        rs = rsqrtf(fmaxf(var, 0.f) + BN_EPS); \
        v = fmaxf((y.X - mu) * rs * g.X + be.X, 0.f); \
        h.X += v;
    BN1(x) BN1(y) BN1(z) BN1(w)
    #undef BN1
    ((float4*)d_h)[i] = h;
}

// ---------------- tail: last-layer bn folded into pool + pred ----------------
__global__ void k_poolpred(const int* __restrict__ gids,
                           const float* __restrict__ gamma,
                           const float* __restrict__ beta,
                           const float* __restrict__ W,
                           const float* __restrict__ b,
                           float* __restrict__ out) {
    __shared__ float red[256];
    __shared__ float gs[EMBED];
    __shared__ int range[2];
    int g = blockIdx.x, tid = threadIdx.x;
    int c = tid & 63, grp = tid >> 6;
    if (tid < 2) {
        int target = g + tid;
        int lo = 0, hi = NNODES;
        while (lo < hi) { int m = (lo + hi) >> 1; if (gids[m] < target) lo = m + 1; else hi = m; }
        range[tid] = lo;
    }
    // per-channel BN constants for last layer
    const float invN = 1.f / (float)NNODES;
    const float* st = d_Z.stats + (NCONV - 1) * 128;
    float mu = st[c] * invN;
    float var = st[64 + c] * invN - mu * mu;
    float rsg = rsqrtf(fmaxf(var, 0.f) + BN_EPS) * gamma[c];
    float be = beta[c];
    __syncthreads();
    int start = range[0], end = range[1];
    float acc = 0.f;
    for (int n = start + grp; n < end; n += 4) {
        float hv = d_h[(size_t)n * EMBED + c];
        float yv = d_y[(size_t)n * EMBED + c];
        acc += hv + (yv - mu) * rsg + be;
    }
    red[tid] = acc;
    __syncthreads();
    if (grp == 0) {
        float s = red[c] + red[64 + c] + red[128 + c] + red[192 + c];
        int cntg = end - start;
        gs[c] = s / (float)(cntg > 0 ? cntg : 1);
    }
    __syncthreads();
    if (tid < OUTDIM) {
        float a = b[tid];
        #pragma unroll
        for (int k = 0; k < EMBED; k++) a += gs[k] * W[k * OUTDIM + tid];
        out[g * OUTDIM + tid] = a;
    }
}

// ---------------- launch ----------------
extern "C" void kernel_launch(void* const* d_in, const int* in_sizes, int n_in,
                              void* d_out, int out_size) {
    const int*   nfeat      = (const int*)d_in[0];
    const int*   efeat      = (const int*)d_in[1];
    const int*   src        = (const int*)d_in[2];
    const int*   dst        = (const int*)d_in[3];
    const int*   gids       = (const int*)d_in[4];
    const float* atom_embed = (const float*)d_in[5];
    const float* bond_embed = (const float*)d_in[6];
    const float* conv_W     = (const float*)d_in[7];
    const float* conv_b     = (const float*)d_in[8];
    const float* bn_gamma   = (const float*)d_in[9];
    const float* bn_beta    = (const float*)d_in[10];
    const float* pred_W     = (const float*)d_in[11];
    const float* pred_b     = (const float*)d_in[12];
    float* out = (float*)d_out;

    void* zp = nullptr;
    cudaGetSymbolAddress(&zp, d_Z);
    cudaMemsetAsync(zp, 0, sizeof(ZBuf), 0);

    k_setup<<<SCAN_BLOCKS, 256>>>(nfeat, (const float4*)atom_embed, dst);
    k_fill<<<(NEDGES + 255) / 256, 256>>>(src, efeat, dst);

    for (int i = 0; i < NCONV; i++) {
        k_msg<<<(NNODES + 7) / 8, 256>>>(bond_embed + i * 5 * EMBED);
        k_gemm<<<2 * SCAN_BLOCKS, 256>>>(conv_W + i * EMBED * EMBED,
                                         conv_b + i * EMBED, i);
        if (i < NCONV - 1)
            k_bn<<<(NNODES * 16 + 255) / 256, 256>>>(i, bn_gamma + i * EMBED,
                                                     bn_beta + i * EMBED);
    }

    k_poolpred<<<NGRAPHS, 256>>>(gids, bn_gamma + (NCONV - 1) * EMBED,
                                 bn_beta + (NCONV - 1) * EMBED,
                                 pred_W, pred_b, out);
}

// round 15
// speedup vs baseline: 1.7104x; 1.7104x over previous
#include <cuda_runtime.h>

#define NNODES 100000
#define NEDGES 1000000
#define NGRAPHS 1000
#define EMBED 64
#define OUTDIM 128
#define NCONV 3
#define BN_EPS 1e-5f

#define SCAN_BLOCKS 391                       // ceil(NNODES/256); all resident
#define EDGE_PER_BLK ((NEDGES + SCAN_BLOCKS - 1) / SCAN_BLOCKS)   // 2558

typedef unsigned long long u64;

// ---------------- scratch (no allocs allowed) ----------------
// stats MUST be 16B-aligned (float4 loads) -> placed first.
struct alignas(16) ZBuf {     // zeroed via one cudaMemsetAsync each call
    float stats[NCONV * 2 * EMBED];   // offset 0, 1536 B (mult of 16)
    int   deg[NNODES];
    int   cnt1;                // setup barrier 1 (counts done)
    int   cnt2;                // setup barrier 2 arrivals
    int   done2;               // setup barrier 2 flag
};
__device__ ZBuf d_Z;

__device__ float d_h[NNODES * EMBED];      // node features
__device__ float d_t[NNODES * EMBED];      // agg + h (GEMM input)
__device__ float d_y[NNODES * EMBED];      // GEMM output (pre-BN)
__device__ int   d_rowptr[NNODES + 1];
__device__ int   d_cursor[NNODES];
__device__ float d_inv[NNODES];            // 1/max(deg,1)
__device__ int   d_aggr[512];
__device__ int   d_off[512];
__device__ unsigned d_edge[NEDGES];        // packed: (src << 8) | efeat
__device__ float d_gn[NGRAPHS * EMBED];

// ---------------- f32x2 helpers ----------------
__device__ __forceinline__ u64 ffma2(u64 a, u64 b, u64 c) {
    u64 d;
    asm("fma.rn.f32x2 %0, %1, %2, %3;" : "=l"(d) : "l"(a), "l"(b), "l"(c));
    return d;
}
__device__ __forceinline__ u64 pack2(float x) {
    u64 d;
    asm("mov.b64 %0, {%1, %1};" : "=l"(d) : "f"(x));
    return d;
}

// ---------------- fused setup: embed + degree count + scan ----------------
// 391 blocks, all resident: two in-kernel spin barriers are deadlock-free.
__global__ void __launch_bounds__(256) k_setup(const int* __restrict__ nfeat,
                                               const float4* __restrict__ atom_embed,
                                               const int* __restrict__ dst) {
    __shared__ int s[256];
    __shared__ int s2[256];
    __shared__ int sdone;
    int t = threadIdx.x, bid = blockIdx.x;

    // phase A1: embed — thread-per-float4, coalesced (16 iters of 256 lanes)
    {
        int base = bid * 4096;                      // 256 nodes * 16 float4
        #pragma unroll 4
        for (int j = 0; j < 16; j++) {
            int idx = base + j * 256 + t;
            if (idx < NNODES * 16) {
                int n = idx >> 4, c4 = idx & 15;
                ((float4*)d_h)[idx] = atom_embed[nfeat[n] * 16 + c4];
            }
        }
    }
    // phase A2: degree count over this block's edge slice
    {
        int e0 = bid * EDGE_PER_BLK;
        int e1 = e0 + EDGE_PER_BLK; if (e1 > NEDGES) e1 = NEDGES;
        for (int e = e0 + t; e < e1; e += 256)
            atomicAdd(&d_Z.deg[dst[e]], 1);
    }
    // barrier 1: all counts globally visible
    __syncthreads();
    if (t == 0) {
        __threadfence();
        atomicAdd(&d_Z.cnt1, 1);
        while (atomicAdd(&d_Z.cnt1, 0) < SCAN_BLOCKS) __nanosleep(40);
    }
    __syncthreads();

    // phase B: block-local scan + cross-block offsets (second spin barrier)
    int i = bid * 256 + t;
    int v = (i < NNODES) ? __ldcg(&d_Z.deg[i]) : 0;
    s[t] = v;
    __syncthreads();
    #pragma unroll
    for (int off = 1; off < 256; off <<= 1) {
        int u = (t >= off) ? s[t - off] : 0;
        __syncthreads();
        s[t] += u;
        __syncthreads();
    }
    int lexcl = s[t] - v;
    int agg = s[255];
    if (t == 0) {
        d_aggr[bid] = agg;
        __threadfence();
        int old = atomicAdd(&d_Z.cnt2, 1);
        sdone = (old == SCAN_BLOCKS - 1);
    }
    __syncthreads();
    if (sdone) {
        int a0 = (2 * t < SCAN_BLOCKS) ? __ldcg(&d_aggr[2 * t]) : 0;
        int a1 = (2 * t + 1 < SCAN_BLOCKS) ? __ldcg(&d_aggr[2 * t + 1]) : 0;
        s2[t] = a0 + a1;
        __syncthreads();
        #pragma unroll
        for (int off = 1; off < 256; off <<= 1) {
            int u = (t >= off) ? s2[t - off] : 0;
            __syncthreads();
            s2[t] += u;
            __syncthreads();
        }
        int ex = s2[t] - (a0 + a1);
        d_off[2 * t] = ex;
        d_off[2 * t + 1] = ex + a0;
        if (t == 255) d_rowptr[NNODES] = s2[255];
        __threadfence();
        if (t == 0) atomicExch(&d_Z.done2, 1);
    }
    if (t == 0) {
        while (atomicAdd(&d_Z.done2, 0) == 0) __nanosleep(40);
    }
    __syncthreads();
    int boff = __ldcg(&d_off[bid]);
    if (i < NNODES) {
        int r = lexcl + boff;
        d_rowptr[i] = r;
        d_cursor[i] = r;
        d_inv[i] = 1.f / (float)(v > 0 ? v : 1);
    }
}

__global__ void k_fill(const int* __restrict__ src,
                       const int* __restrict__ efeat,
                       const int* __restrict__ dst) {
    int e = blockIdx.x * blockDim.x + threadIdx.x;
    if (e >= NEDGES) return;
    int p = atomicAdd(&d_cursor[dst[e]], 1);
    d_edge[p] = ((unsigned)src[e] << 8) | (unsigned)efeat[e];
}

// ---------------- per-layer kernels ----------------
// warp per node, lane covers 2 channels (float2). 4x-unrolled edge loop with
// byte-offset packed edges. __launch_bounds__(256, 8) pins regs to 32 so all
// 8 blocks fit per SM (measured occupancy sweet spot).
__global__ void __launch_bounds__(256, 8) k_msg(const float* __restrict__ bond) {
    __shared__ __align__(16) float bsh[5 * EMBED];
    int tid = threadIdx.x;
    for (int i = tid; i < 5 * EMBED; i += 256) bsh[i] = bond[i];
    __syncthreads();
    int warp = tid >> 5, lane = tid & 31;
    int node = blockIdx.x * 8 + warp;
    if (node >= NNODES) return;
    int rs = d_rowptr[node], re = d_rowptr[node + 1];
    const char* hb = (const char*)d_h + lane * 8;
    const char* bb = (const char*)bsh + lane * 8;
    float2 a0 = make_float2(0.f, 0.f), a1 = a0, a2 = a0, a3 = a0;
    int e = rs;
    for (; e + 3 < re; e += 4) {
        unsigned p0 = d_edge[e],     p1 = d_edge[e + 1];
        unsigned p2 = d_edge[e + 2], p3 = d_edge[e + 3];
        float2 h0 = *(const float2*)(hb + (p0 & 0xFFFFFF00u));
        float2 h1 = *(const float2*)(hb + (p1 & 0xFFFFFF00u));
        float2 h2 = *(const float2*)(hb + (p2 & 0xFFFFFF00u));
        float2 h3 = *(const float2*)(hb + (p3 & 0xFFFFFF00u));
        float2 b0 = *(const float2*)(bb + ((p0 & 255u) << 8));
        float2 b1 = *(const float2*)(bb + ((p1 & 255u) << 8));
        float2 b2 = *(const float2*)(bb + ((p2 & 255u) << 8));
        float2 b3 = *(const float2*)(bb + ((p3 & 255u) << 8));
        a0.x += fmaxf(b0.x + h0.x, 0.f);  a0.y += fmaxf(b0.y + h0.y, 0.f);
        a1.x += fmaxf(b1.x + h1.x, 0.f);  a1.y += fmaxf(b1.y + h1.y, 0.f);
        a2.x += fmaxf(b2.x + h2.x, 0.f);  a2.y += fmaxf(b2.y + h2.y, 0.f);
        a3.x += fmaxf(b3.x + h3.x, 0.f);  a3.y += fmaxf(b3.y + h3.y, 0.f);
    }
    for (; e < re; e++) {
        unsigned p0 = d_edge[e];
        float2 h0 = *(const float2*)(hb + (p0 & 0xFFFFFF00u));
        float2 b0 = *(const float2*)(bb + ((p0 & 255u) << 8));
        a0.x += fmaxf(b0.x + h0.x, 0.f);  a0.y += fmaxf(b0.y + h0.y, 0.f);
    }
    a0.x += a1.x + a2.x + a3.x;
    a0.y += a1.y + a2.y + a3.y;
    float inv = d_inv[node];
    float2 hn = ((const float2*)(d_h + (size_t)node * EMBED))[lane];
    float2 o;
    o.x = a0.x * inv + hn.x;
    o.y = a0.y * inv + hn.y;
    ((float2*)(d_t + (size_t)node * EMBED))[lane] = o;
}

// thread per node: y = t @ W + b (packed f32x2 FMA) + fused per-block stats.
// High-register operating point is INTENTIONAL (measured best at 139 regs /
// 1 block/SM): ptxas uses the register headroom to software-pipeline the tv
// global loads and batch LDS. unroll 4 on the k4 loop raises tv-load MLP to 4
// (fully overlaps L2 latency per B300 model).
__global__ void __launch_bounds__(256) k_gemm(const float* __restrict__ W,
                                              const float* __restrict__ b,
                                              int layer) {
    __shared__ ulonglong2 Ws[EMBED * 16];
    __shared__ float4 ssum[256], ssq[256];
    int tid = threadIdx.x;
    for (int i = tid; i < EMBED * 16; i += 256) Ws[i] = ((const ulonglong2*)W)[i];
    __syncthreads();
    int node = blockIdx.x * 256 + tid;
    if (node < NNODES) {
        u64 acc[32];
        const u64* bp = (const u64*)b;
        #pragma unroll
        for (int i = 0; i < 32; i++) acc[i] = bp[i];
        const float4* tp = (const float4*)(d_t + (size_t)node * EMBED);
        #pragma unroll 4
        for (int k4 = 0; k4 < 16; k4++) {
            float4 tv = tp[k4];
            #pragma unroll
            for (int j = 0; j < 4; j++) {
                float tk = (j == 0) ? tv.x : (j == 1) ? tv.y : (j == 2) ? tv.z : tv.w;
                u64 tkk = pack2(tk);
                int k = k4 * 4 + j;
                #pragma unroll
                for (int c8 = 0; c8 < 16; c8++) {
                    ulonglong2 w = Ws[k * 16 + c8];
                    acc[2 * c8]     = ffma2(tkk, w.x, acc[2 * c8]);
                    acc[2 * c8 + 1] = ffma2(tkk, w.y, acc[2 * c8 + 1]);
                }
            }
        }
        ulonglong2* yp = (ulonglong2*)(d_y + (size_t)node * EMBED);
        #pragma unroll
        for (int i = 0; i < 16; i++)
            yp[i] = make_ulonglong2(acc[2 * i], acc[2 * i + 1]);
    }
    __syncthreads();   // all y-rows of this block visible (cta scope)
    int c4 = tid & 15, grp = tid >> 4;
    int base = blockIdx.x * 256;
    float4 sum = make_float4(0.f, 0.f, 0.f, 0.f), sq = sum;
    for (int r = grp; r < 256; r += 16) {
        int row = base + r;
        if (row >= NNODES) break;
        float4 v = ((const float4*)d_y)[row * 16 + c4];
        sum.x += v.x; sum.y += v.y; sum.z += v.z; sum.w += v.w;
        sq.x += v.x * v.x; sq.y += v.y * v.y; sq.z += v.z * v.z; sq.w += v.w * v.w;
    }
    ssum[tid] = sum; ssq[tid] = sq;
    __syncthreads();
    if (grp == 0) {
        #pragma unroll
        for (int g = 1; g < 16; g++) {
            float4 a = ssum[g * 16 + c4], q = ssq[g * 16 + c4];
            sum.x += a.x; sum.y += a.y; sum.z += a.z; sum.w += a.w;
            sq.x += q.x; sq.y += q.y; sq.z += q.z; sq.w += q.w;
        }
        float* st = d_Z.stats + layer * 128;
        atomicAdd(&st[c4 * 4 + 0], sum.x);
        atomicAdd(&st[c4 * 4 + 1], sum.y);
        atomicAdd(&st[c4 * 4 + 2], sum.z);
        atomicAdd(&st[c4 * 4 + 3], sum.w);
        atomicAdd(&st[64 + c4 * 4 + 0], sq.x);
        atomicAdd(&st[64 + c4 * 4 + 1], sq.y);
        atomicAdd(&st[64 + c4 * 4 + 2], sq.z);
        atomicAdd(&st[64 + c4 * 4 + 3], sq.w);
    }
}

// normalize + gamma/beta + relu + residual (h += act), float4 wide (layers 0,1)
__global__ void k_bn(int layer, const float* __restrict__ gamma,
                     const float* __restrict__ beta) {
    int i = blockIdx.x * blockDim.x + threadIdx.x;   // float4 index
    if (i >= NNODES * 16) return;
    int c4 = i & 15;
    const float* st = d_Z.stats + layer * 128;
    const float invN = 1.f / (float)NNODES;
    float4 s1 = ((const float4*)st)[c4];
    float4 s2 = ((const float4*)(st + 64))[c4];
    float4 g  = ((const float4*)gamma)[c4];
    float4 be = ((const float4*)beta)[c4];
    float4 y  = ((const float4*)d_y)[i];
    float4 h  = ((const float4*)d_h)[i];
    float mu, var, rs, v;
    #define BN1(X) \
        mu = s1.X * invN; var = s2.X * invN - mu * mu; \
        rs = rsqrtf(fmaxf(var, 0.f) + BN_EPS); \
        v = fmaxf((y.X - mu) * rs * g.X + be.X, 0.f); \
        h.X += v;
    BN1(x) BN1(y) BN1(z) BN1(w)
    #undef BN1
    ((float4*)d_h)[i] = h;
}

// ---------------- tail: last-layer bn folded into pool + pred ----------------
__global__ void k_poolpred(const int* __restrict__ gids,
                           const float* __restrict__ gamma,
                           const float* __restrict__ beta,
                           const float* __restrict__ W,
                           const float* __restrict__ b,
                           float* __restrict__ out) {
    __shared__ float red[256];
    __shared__ float gs[EMBED];
    __shared__ int range[2];
    int g = blockIdx.x, tid = threadIdx.x;
    int c = tid & 63, grp = tid >> 6;
    if (tid < 2) {
        int target = g + tid;
        int lo = 0, hi = NNODES;
        while (lo < hi) { int m = (lo + hi) >> 1; if (gids[m] < target) lo = m + 1; else hi = m; }
        range[tid] = lo;
    }
    // per-channel BN constants for last layer
    const float invN = 1.f / (float)NNODES;
    const float* st = d_Z.stats + (NCONV - 1) * 128;
    float mu = st[c] * invN;
    float var = st[64 + c] * invN - mu * mu;
    float rsg = rsqrtf(fmaxf(var, 0.f) + BN_EPS) * gamma[c];
    float be = beta[c];
    __syncthreads();
    int start = range[0], end = range[1];
    float acc = 0.f;
    for (int n = start + grp; n < end; n += 4) {
        float hv = d_h[(size_t)n * EMBED + c];
        float yv = d_y[(size_t)n * EMBED + c];
        acc += hv + (yv - mu) * rsg + be;
    }
    red[tid] = acc;
    __syncthreads();
    if (grp == 0) {
        float s = red[c] + red[64 + c] + red[128 + c] + red[192 + c];
        int cntg = end - start;
        gs[c] = s / (float)(cntg > 0 ? cntg : 1);
    }
    __syncthreads();
    if (tid < OUTDIM) {
        float a = b[tid];
        #pragma unroll
        for (int k = 0; k < EMBED; k++) a += gs[k] * W[k * OUTDIM + tid];
        out[g * OUTDIM + tid] = a;
    }
}

// ---------------- launch ----------------
extern "C" void kernel_launch(void* const* d_in, const int* in_sizes, int n_in,
                              void* d_out, int out_size) {
    const int*   nfeat      = (const int*)d_in[0];
    const int*   efeat      = (const int*)d_in[1];
    const int*   src        = (const int*)d_in[2];
    const int*   dst        = (const int*)d_in[3];
    const int*   gids       = (const int*)d_in[4];
    const float* atom_embed = (const float*)d_in[5];
    const float* bond_embed = (const float*)d_in[6];
    const float* conv_W     = (const float*)d_in[7];
    const float* conv_b     = (const float*)d_in[8];
    const float* bn_gamma   = (const float*)d_in[9];
    const float* bn_beta    = (const float*)d_in[10];
    const float* pred_W     = (const float*)d_in[11];
    const float* pred_b     = (const float*)d_in[12];
    float* out = (float*)d_out;

    void* zp = nullptr;
    cudaGetSymbolAddress(&zp, d_Z);
    cudaMemsetAsync(zp, 0, sizeof(ZBuf), 0);

    k_setup<<<SCAN_BLOCKS, 256>>>(nfeat, (const float4*)atom_embed, dst);
    k_fill<<<(NEDGES + 255) / 256, 256>>>(src, efeat, dst);

    for (int i = 0; i < NCONV; i++) {
        k_msg<<<(NNODES + 7) / 8, 256>>>(bond_embed + i * 5 * EMBED);
        k_gemm<<<SCAN_BLOCKS, 256>>>(conv_W + i * EMBED * EMBED,
                                     conv_b + i * EMBED, i);
        if (i < NCONV - 1)
            k_bn<<<(NNODES * 16 + 255) / 256, 256>>>(i, bn_gamma + i * EMBED,
                                                     bn_beta + i * EMBED);
    }

    k_poolpred<<<NGRAPHS, 256>>>(gids, bn_gamma + (NCONV - 1) * EMBED,
                                 bn_beta + (NCONV - 1) * EMBED,
                                 pred_W, pred_b, out);
}

// round 16
// speedup vs baseline: 1.7661x; 1.0326x over previous
#include <cuda_runtime.h>

#define NNODES 100000
#define NEDGES 1000000
#define NGRAPHS 1000
#define EMBED 64
#define OUTDIM 128
#define NCONV 3
#define BN_EPS 1e-5f

#define SCAN_BLOCKS 391                       // ceil(NNODES/256); all resident
#define EDGE_PER_BLK ((NEDGES + SCAN_BLOCKS - 1) / SCAN_BLOCKS)   // 2558

typedef unsigned long long u64;

// ---------------- scratch (no allocs allowed) ----------------
// stats MUST be 16B-aligned (float4 loads) -> placed first.
struct alignas(16) ZBuf {     // zeroed via one cudaMemsetAsync each call
    float stats[NCONV * 2 * EMBED];   // offset 0, 1536 B (mult of 16)
    int   deg[NNODES];
    int   cnt1;                // setup barrier 1 (counts done)
    int   cnt2;                // setup barrier 2 arrivals
    int   done2;               // setup barrier 2 flag
};
__device__ ZBuf d_Z;

__device__ float d_h[NNODES * EMBED];      // node features
__device__ float d_t[NNODES * EMBED];      // agg + h (GEMM input)
__device__ float d_y[NNODES * EMBED];      // GEMM output (pre-BN)
__device__ int   d_rowptr[NNODES + 1];
__device__ int   d_cursor[NNODES];
__device__ float d_inv[NNODES];            // 1/max(deg,1)
__device__ int   d_aggr[512];
__device__ int   d_off[512];
__device__ unsigned d_edge[NEDGES];        // packed: (src << 8) | efeat
__device__ float d_gn[NGRAPHS * EMBED];

// ---------------- f32x2 helpers ----------------
__device__ __forceinline__ u64 ffma2(u64 a, u64 b, u64 c) {
    u64 d;
    asm("fma.rn.f32x2 %0, %1, %2, %3;" : "=l"(d) : "l"(a), "l"(b), "l"(c));
    return d;
}
__device__ __forceinline__ u64 pack2(float x) {
    u64 d;
    asm("mov.b64 %0, {%1, %1};" : "=l"(d) : "f"(x));
    return d;
}

// ---------------- fused setup: embed + degree count + scan ----------------
// 391 blocks, all resident: two in-kernel spin barriers are deadlock-free.
__global__ void __launch_bounds__(256) k_setup(const int* __restrict__ nfeat,
                                               const float4* __restrict__ atom_embed,
                                               const int* __restrict__ dst) {
    __shared__ int s[256];
    __shared__ int s2[256];
    __shared__ int sdone;
    int t = threadIdx.x, bid = blockIdx.x;

    // phase A1: embed — thread-per-float4, coalesced (16 iters of 256 lanes)
    {
        int base = bid * 4096;                      // 256 nodes * 16 float4
        #pragma unroll 4
        for (int j = 0; j < 16; j++) {
            int idx = base + j * 256 + t;
            if (idx < NNODES * 16) {
                int n = idx >> 4, c4 = idx & 15;
                ((float4*)d_h)[idx] = atom_embed[nfeat[n] * 16 + c4];
            }
        }
    }
    // phase A2: degree count over this block's edge slice
    {
        int e0 = bid * EDGE_PER_BLK;
        int e1 = e0 + EDGE_PER_BLK; if (e1 > NEDGES) e1 = NEDGES;
        for (int e = e0 + t; e < e1; e += 256)
            atomicAdd(&d_Z.deg[dst[e]], 1);
    }
    // barrier 1: all counts globally visible
    __syncthreads();
    if (t == 0) {
        __threadfence();
        atomicAdd(&d_Z.cnt1, 1);
        while (atomicAdd(&d_Z.cnt1, 0) < SCAN_BLOCKS) __nanosleep(40);
    }
    __syncthreads();

    // phase B: block-local scan + cross-block offsets (second spin barrier)
    int i = bid * 256 + t;
    int v = (i < NNODES) ? __ldcg(&d_Z.deg[i]) : 0;
    s[t] = v;
    __syncthreads();
    #pragma unroll
    for (int off = 1; off < 256; off <<= 1) {
        int u = (t >= off) ? s[t - off] : 0;
        __syncthreads();
        s[t] += u;
        __syncthreads();
    }
    int lexcl = s[t] - v;
    int agg = s[255];
    if (t == 0) {
        d_aggr[bid] = agg;
        __threadfence();
        int old = atomicAdd(&d_Z.cnt2, 1);
        sdone = (old == SCAN_BLOCKS - 1);
    }
    __syncthreads();
    if (sdone) {
        int a0 = (2 * t < SCAN_BLOCKS) ? __ldcg(&d_aggr[2 * t]) : 0;
        int a1 = (2 * t + 1 < SCAN_BLOCKS) ? __ldcg(&d_aggr[2 * t + 1]) : 0;
        s2[t] = a0 + a1;
        __syncthreads();
        #pragma unroll
        for (int off = 1; off < 256; off <<= 1) {
            int u = (t >= off) ? s2[t - off] : 0;
            __syncthreads();
            s2[t] += u;
            __syncthreads();
        }
        int ex = s2[t] - (a0 + a1);
        d_off[2 * t] = ex;
        d_off[2 * t + 1] = ex + a0;
        if (t == 255) d_rowptr[NNODES] = s2[255];
        __threadfence();
        if (t == 0) atomicExch(&d_Z.done2, 1);
    }
    if (t == 0) {
        while (atomicAdd(&d_Z.done2, 0) == 0) __nanosleep(40);
    }
    __syncthreads();
    int boff = __ldcg(&d_off[bid]);
    if (i < NNODES) {
        int r = lexcl + boff;
        d_rowptr[i] = r;
        d_cursor[i] = r;
        d_inv[i] = 1.f / (float)(v > 0 ? v : 1);
    }
}

__global__ void k_fill(const int* __restrict__ src,
                       const int* __restrict__ efeat,
                       const int* __restrict__ dst) {
    int e = blockIdx.x * blockDim.x + threadIdx.x;
    if (e >= NEDGES) return;
    int p = atomicAdd(&d_cursor[dst[e]], 1);
    d_edge[p] = ((unsigned)src[e] << 8) | (unsigned)efeat[e];
}

// ---------------- per-layer kernels ----------------
// warp per node, lane covers 2 channels (float2). 4x-unrolled edge loop with
// byte-offset packed edges. __launch_bounds__(256, 8) pins regs to 32 so all
// 8 blocks fit per SM (measured occupancy sweet spot).
__global__ void __launch_bounds__(256, 8) k_msg(const float* __restrict__ bond) {
    __shared__ __align__(16) float bsh[5 * EMBED];
    int tid = threadIdx.x;
    for (int i = tid; i < 5 * EMBED; i += 256) bsh[i] = bond[i];
    __syncthreads();
    int warp = tid >> 5, lane = tid & 31;
    int node = blockIdx.x * 8 + warp;
    if (node >= NNODES) return;
    int rs = d_rowptr[node], re = d_rowptr[node + 1];
    const char* hb = (const char*)d_h + lane * 8;
    const char* bb = (const char*)bsh + lane * 8;
    float2 a0 = make_float2(0.f, 0.f), a1 = a0, a2 = a0, a3 = a0;
    int e = rs;
    for (; e + 3 < re; e += 4) {
        unsigned p0 = d_edge[e],     p1 = d_edge[e + 1];
        unsigned p2 = d_edge[e + 2], p3 = d_edge[e + 3];
        float2 h0 = *(const float2*)(hb + (p0 & 0xFFFFFF00u));
        float2 h1 = *(const float2*)(hb + (p1 & 0xFFFFFF00u));
        float2 h2 = *(const float2*)(hb + (p2 & 0xFFFFFF00u));
        float2 h3 = *(const float2*)(hb + (p3 & 0xFFFFFF00u));
        float2 b0 = *(const float2*)(bb + ((p0 & 255u) << 8));
        float2 b1 = *(const float2*)(bb + ((p1 & 255u) << 8));
        float2 b2 = *(const float2*)(bb + ((p2 & 255u) << 8));
        float2 b3 = *(const float2*)(bb + ((p3 & 255u) << 8));
        a0.x += fmaxf(b0.x + h0.x, 0.f);  a0.y += fmaxf(b0.y + h0.y, 0.f);
        a1.x += fmaxf(b1.x + h1.x, 0.f);  a1.y += fmaxf(b1.y + h1.y, 0.f);
        a2.x += fmaxf(b2.x + h2.x, 0.f);  a2.y += fmaxf(b2.y + h2.y, 0.f);
        a3.x += fmaxf(b3.x + h3.x, 0.f);  a3.y += fmaxf(b3.y + h3.y, 0.f);
    }
    for (; e < re; e++) {
        unsigned p0 = d_edge[e];
        float2 h0 = *(const float2*)(hb + (p0 & 0xFFFFFF00u));
        float2 b0 = *(const float2*)(bb + ((p0 & 255u) << 8));
        a0.x += fmaxf(b0.x + h0.x, 0.f);  a0.y += fmaxf(b0.y + h0.y, 0.f);
    }
    a0.x += a1.x + a2.x + a3.x;
    a0.y += a1.y + a2.y + a3.y;
    float inv = d_inv[node];
    float2 hn = ((const float2*)(d_h + (size_t)node * EMBED))[lane];
    float2 o;
    o.x = a0.x * inv + hn.x;
    o.y = a0.y * inv + hn.y;
    ((float2*)(d_t + (size_t)node * EMBED))[lane] = o;
}

// GEMM: TWO nodes per thread, channel-split. Thread (pair, half) computes
// nodes {2*pair, 2*pair+1} x channels [half*32, half*32+32). Each Ws LDS.128
// (a 32-lane broadcast costing 4 smem wavefront-cycles) now feeds FFMA2s for
// two nodes -> per-node smem return traffic HALVES (R15 profile showed smem
// return BW as the binding wall: L1 59%, occ 12%, issue 21%). No launch_bounds
// cap: ptxas keeps register headroom for load pipelining (R13/R14 lesson).
// Block still covers 256 nodes (128 pairs x 2 halves); fused stats unchanged.
__global__ void k_gemm(const float* __restrict__ W,
                       const float* __restrict__ b,
                       int layer) {
    __shared__ ulonglong2 Ws[EMBED * 16];
    __shared__ float4 ssum[256], ssq[256];
    int tid = threadIdx.x;
    for (int i = tid; i < EMBED * 16; i += 256) Ws[i] = ((const ulonglong2*)W)[i];
    __syncthreads();
    int pair = tid & 127, half = tid >> 7;
    int n0 = blockIdx.x * 256 + pair * 2;
    int n1 = n0 + 1;
    // clamp row pointers for loads (stores are guarded)
    int n0c = n0 < NNODES ? n0 : NNODES - 1;
    int n1c = n1 < NNODES ? n1 : NNODES - 1;
    {
        const float4* tpA = (const float4*)(d_t + (size_t)n0c * EMBED);
        const float4* tpB = (const float4*)(d_t + (size_t)n1c * EMBED);
        u64 accA[16], accB[16];
        const u64* bp = (const u64*)b + half * 16;
        #pragma unroll
        for (int i = 0; i < 16; i++) { accA[i] = bp[i]; accB[i] = bp[i]; }
        #pragma unroll 4
        for (int k4 = 0; k4 < 16; k4++) {
            float4 ta = tpA[k4];
            float4 tb = tpB[k4];
            #pragma unroll
            for (int j = 0; j < 4; j++) {
                float fa = (j == 0) ? ta.x : (j == 1) ? ta.y : (j == 2) ? ta.z : ta.w;
                float fb = (j == 0) ? tb.x : (j == 1) ? tb.y : (j == 2) ? tb.z : tb.w;
                u64 ka = pack2(fa), kb = pack2(fb);
                int k = k4 * 4 + j;
                #pragma unroll
                for (int c8 = 0; c8 < 8; c8++) {
                    ulonglong2 w = Ws[k * 16 + half * 8 + c8];
                    accA[2 * c8]     = ffma2(ka, w.x, accA[2 * c8]);
                    accA[2 * c8 + 1] = ffma2(ka, w.y, accA[2 * c8 + 1]);
                    accB[2 * c8]     = ffma2(kb, w.x, accB[2 * c8]);
                    accB[2 * c8 + 1] = ffma2(kb, w.y, accB[2 * c8 + 1]);
                }
            }
        }
        if (n0 < NNODES) {
            ulonglong2* yp = (ulonglong2*)(d_y + (size_t)n0 * EMBED) + half * 8;
            #pragma unroll
            for (int i = 0; i < 8; i++)
                yp[i] = make_ulonglong2(accA[2 * i], accA[2 * i + 1]);
        }
        if (n1 < NNODES) {
            ulonglong2* yp = (ulonglong2*)(d_y + (size_t)n1 * EMBED) + half * 8;
            #pragma unroll
            for (int i = 0; i < 8; i++)
                yp[i] = make_ulonglong2(accB[2 * i], accB[2 * i + 1]);
        }
    }
    __syncthreads();   // all y-rows of this block visible (cta scope)
    int c4 = tid & 15, grp = tid >> 4;
    int base = blockIdx.x * 256;
    float4 sum = make_float4(0.f, 0.f, 0.f, 0.f), sq = sum;
    for (int r = grp; r < 256; r += 16) {
        int row = base + r;
        if (row >= NNODES) break;
        float4 v = ((const float4*)d_y)[row * 16 + c4];
        sum.x += v.x; sum.y += v.y; sum.z += v.z; sum.w += v.w;
        sq.x += v.x * v.x; sq.y += v.y * v.y; sq.z += v.z * v.z; sq.w += v.w * v.w;
    }
    ssum[tid] = sum; ssq[tid] = sq;
    __syncthreads();
    if (grp == 0) {
        #pragma unroll
        for (int g = 1; g < 16; g++) {
            float4 a = ssum[g * 16 + c4], q = ssq[g * 16 + c4];
            sum.x += a.x; sum.y += a.y; sum.z += a.z; sum.w += a.w;
            sq.x += q.x; sq.y += q.y; sq.z += q.z; sq.w += q.w;
        }
        float* st = d_Z.stats + layer * 128;
        atomicAdd(&st[c4 * 4 + 0], sum.x);
        atomicAdd(&st[c4 * 4 + 1], sum.y);
        atomicAdd(&st[c4 * 4 + 2], sum.z);
        atomicAdd(&st[c4 * 4 + 3], sum.w);
        atomicAdd(&st[64 + c4 * 4 + 0], sq.x);
        atomicAdd(&st[64 + c4 * 4 + 1], sq.y);
        atomicAdd(&st[64 + c4 * 4 + 2], sq.z);
        atomicAdd(&st[64 + c4 * 4 + 3], sq.w);
    }
}

// normalize + gamma/beta + relu + residual (h += act), float4 wide (layers 0,1)
__global__ void k_bn(int layer, const float* __restrict__ gamma,
                     const float* __restrict__ beta) {
    int i = blockIdx.x * blockDim.x + threadIdx.x;   // float4 index
    if (i >= NNODES * 16) return;
    int c4 = i & 15;
    const float* st = d_Z.stats + layer * 128;
    const float invN = 1.f / (float)NNODES;
    float4 s1 = ((const float4*)st)[c4];
    float4 s2 = ((const float4*)(st + 64))[c4];
    float4 g  = ((const float4*)gamma)[c4];
    float4 be = ((const float4*)beta)[c4];
    float4 y  = ((const float4*)d_y)[i];
    float4 h  = ((const float4*)d_h)[i];
    float mu, var, rs, v;
    #define BN1(X) \
        mu = s1.X * invN; var = s2.X * invN - mu * mu; \
        rs = rsqrtf(fmaxf(var, 0.f) + BN_EPS); \
        v = fmaxf((y.X - mu) * rs * g.X + be.X, 0.f); \
        h.X += v;
    BN1(x) BN1(y) BN1(z) BN1(w)
    #undef BN1
    ((float4*)d_h)[i] = h;
}

// ---------------- tail: last-layer bn folded into pool + pred ----------------
__global__ void k_poolpred(const int* __restrict__ gids,
                           const float* __restrict__ gamma,
                           const float* __restrict__ beta,
                           const float* __restrict__ W,
                           const float* __restrict__ b,
                           float* __restrict__ out) {
    __shared__ float red[256];
    __shared__ float gs[EMBED];
    __shared__ int range[2];
    int g = blockIdx.x, tid = threadIdx.x;
    int c = tid & 63, grp = tid >> 6;
    if (tid < 2) {
        int target = g + tid;
        int lo = 0, hi = NNODES;
        while (lo < hi) { int m = (lo + hi) >> 1; if (gids[m] < target) lo = m + 1; else hi = m; }
        range[tid] = lo;
    }
    // per-channel BN constants for last layer
    const float invN = 1.f / (float)NNODES;
    const float* st = d_Z.stats + (NCONV - 1) * 128;
    float mu = st[c] * invN;
    float var = st[64 + c] * invN - mu * mu;
    float rsg = rsqrtf(fmaxf(var, 0.f) + BN_EPS) * gamma[c];
    float be = beta[c];
    __syncthreads();
    int start = range[0], end = range[1];
    float acc = 0.f;
    for (int n = start + grp; n < end; n += 4) {
        float hv = d_h[(size_t)n * EMBED + c];
        float yv = d_y[(size_t)n * EMBED + c];
        acc += hv + (yv - mu) * rsg + be;
    }
    red[tid] = acc;
    __syncthreads();
    if (grp == 0) {
        float s = red[c] + red[64 + c] + red[128 + c] + red[192 + c];
        int cntg = end - start;
        gs[c] = s / (float)(cntg > 0 ? cntg : 1);
    }
    __syncthreads();
    if (tid < OUTDIM) {
        float a = b[tid];
        #pragma unroll
        for (int k = 0; k < EMBED; k++) a += gs[k] * W[k * OUTDIM + tid];
        out[g * OUTDIM + tid] = a;
    }
}

// ---------------- launch ----------------
extern "C" void kernel_launch(void* const* d_in, const int* in_sizes, int n_in,
                              void* d_out, int out_size) {
    const int*   nfeat      = (const int*)d_in[0];
    const int*   efeat      = (const int*)d_in[1];
    const int*   src        = (const int*)d_in[2];
    const int*   dst        = (const int*)d_in[3];
    const int*   gids       = (const int*)d_in[4];
    const float* atom_embed = (const float*)d_in[5];
    const float* bond_embed = (const float*)d_in[6];
    const float* conv_W     = (const float*)d_in[7];
    const float* conv_b     = (const float*)d_in[8];
    const float* bn_gamma   = (const float*)d_in[9];
    const float* bn_beta    = (const float*)d_in[10];
    const float* pred_W     = (const float*)d_in[11];
    const float* pred_b     = (const float*)d_in[12];
    float* out = (float*)d_out;

    void* zp = nullptr;
    cudaGetSymbolAddress(&zp, d_Z);
    cudaMemsetAsync(zp, 0, sizeof(ZBuf), 0);

    k_setup<<<SCAN_BLOCKS, 256>>>(nfeat, (const float4*)atom_embed, dst);
    k_fill<<<(NEDGES + 255) / 256, 256>>>(src, efeat, dst);

    for (int i = 0; i < NCONV; i++) {
        k_msg<<<(NNODES + 7) / 8, 256>>>(bond_embed + i * 5 * EMBED);
        k_gemm<<<SCAN_BLOCKS, 256>>>(conv_W + i * EMBED * EMBED,
                                     conv_b + i * EMBED, i);
        if (i < NCONV - 1)
            k_bn<<<(NNODES * 16 + 255) / 256, 256>>>(i, bn_gamma + i * EMBED,
                                                     bn_beta + i * EMBED);
    }

    k_poolpred<<<NGRAPHS, 256>>>(gids, bn_gamma + (NCONV - 1) * EMBED,
                                 bn_beta + (NCONV - 1) * EMBED,
                                 pred_W, pred_b, out);
}

// round 17
// speedup vs baseline: 2.1188x; 1.1997x over previous
#include <cuda_runtime.h>

#define NNODES 100000
#define NEDGES 1000000
#define NGRAPHS 1000
#define EMBED 64
#define OUTDIM 128
#define NCONV 3
#define BN_EPS 1e-5f

#define SCAN_BLOCKS 391                       // ceil(NNODES/256); all resident
#define EDGE_PER_BLK ((NEDGES + SCAN_BLOCKS - 1) / SCAN_BLOCKS)   // 2558

#define TB_STRIDE 17                          // float4 per padded row (68 floats)
#define GEMM_SMEM (16384 + 256 * TB_STRIDE * 16 + 8192)   // Ws + tbuf + stats

typedef unsigned long long u64;

// ---------------- scratch (no allocs allowed) ----------------
// stats MUST be 16B-aligned (float4 loads) -> placed first.
struct alignas(16) ZBuf {     // zeroed via one cudaMemsetAsync each call
    float stats[NCONV * 2 * EMBED];   // offset 0, 1536 B (mult of 16)
    int   deg[NNODES];
    int   cnt1;                // setup barrier 1 (counts done)
    int   cnt2;                // setup barrier 2 arrivals
    int   done2;               // setup barrier 2 flag
};
__device__ ZBuf d_Z;

__device__ float d_h[NNODES * EMBED];      // node features
__device__ float d_t[NNODES * EMBED];      // agg + h (GEMM input)
__device__ float d_y[NNODES * EMBED];      // GEMM output (pre-BN)
__device__ int   d_rowptr[NNODES + 1];
__device__ int   d_cursor[NNODES];
__device__ float d_inv[NNODES];            // 1/max(deg,1)
__device__ int   d_aggr[512];
__device__ int   d_off[512];
__device__ unsigned d_edge[NEDGES];        // packed: (src << 8) | efeat
__device__ float d_gn[NGRAPHS * EMBED];

// ---------------- f32x2 helpers ----------------
__device__ __forceinline__ u64 ffma2(u64 a, u64 b, u64 c) {
    u64 d;
    asm("fma.rn.f32x2 %0, %1, %2, %3;" : "=l"(d) : "l"(a), "l"(b), "l"(c));
    return d;
}
__device__ __forceinline__ u64 pack2(float x) {
    u64 d;
    asm("mov.b64 %0, {%1, %1};" : "=l"(d) : "f"(x));
    return d;
}

// ---------------- fused setup: embed + degree count + scan ----------------
// 391 blocks, all resident: two in-kernel spin barriers are deadlock-free.
__global__ void __launch_bounds__(256) k_setup(const int* __restrict__ nfeat,
                                               const float4* __restrict__ atom_embed,
                                               const int* __restrict__ dst) {
    __shared__ int s[256];
    __shared__ int s2[256];
    __shared__ int sdone;
    int t = threadIdx.x, bid = blockIdx.x;

    // phase A1: embed — thread-per-float4, coalesced (16 iters of 256 lanes)
    {
        int base = bid * 4096;                      // 256 nodes * 16 float4
        #pragma unroll 4
        for (int j = 0; j < 16; j++) {
            int idx = base + j * 256 + t;
            if (idx < NNODES * 16) {
                int n = idx >> 4, c4 = idx & 15;
                ((float4*)d_h)[idx] = atom_embed[nfeat[n] * 16 + c4];
            }
        }
    }
    // phase A2: degree count over this block's edge slice
    {
        int e0 = bid * EDGE_PER_BLK;
        int e1 = e0 + EDGE_PER_BLK; if (e1 > NEDGES) e1 = NEDGES;
        for (int e = e0 + t; e < e1; e += 256)
            atomicAdd(&d_Z.deg[dst[e]], 1);
    }
    // barrier 1: all counts globally visible
    __syncthreads();
    if (t == 0) {
        __threadfence();
        atomicAdd(&d_Z.cnt1, 1);
        while (atomicAdd(&d_Z.cnt1, 0) < SCAN_BLOCKS) __nanosleep(40);
    }
    __syncthreads();

    // phase B: block-local scan + cross-block offsets (second spin barrier)
    int i = bid * 256 + t;
    int v = (i < NNODES) ? __ldcg(&d_Z.deg[i]) : 0;
    s[t] = v;
    __syncthreads();
    #pragma unroll
    for (int off = 1; off < 256; off <<= 1) {
        int u = (t >= off) ? s[t - off] : 0;
        __syncthreads();
        s[t] += u;
        __syncthreads();
    }
    int lexcl = s[t] - v;
    int agg = s[255];
    if (t == 0) {
        d_aggr[bid] = agg;
        __threadfence();
        int old = atomicAdd(&d_Z.cnt2, 1);
        sdone = (old == SCAN_BLOCKS - 1);
    }
    __syncthreads();
    if (sdone) {
        int a0 = (2 * t < SCAN_BLOCKS) ? __ldcg(&d_aggr[2 * t]) : 0;
        int a1 = (2 * t + 1 < SCAN_BLOCKS) ? __ldcg(&d_aggr[2 * t + 1]) : 0;
        s2[t] = a0 + a1;
        __syncthreads();
        #pragma unroll
        for (int off = 1; off < 256; off <<= 1) {
            int u = (t >= off) ? s2[t - off] : 0;
            __syncthreads();
            s2[t] += u;
            __syncthreads();
        }
        int ex = s2[t] - (a0 + a1);
        d_off[2 * t] = ex;
        d_off[2 * t + 1] = ex + a0;
        if (t == 255) d_rowptr[NNODES] = s2[255];
        __threadfence();
        if (t == 0) atomicExch(&d_Z.done2, 1);
    }
    if (t == 0) {
        while (atomicAdd(&d_Z.done2, 0) == 0) __nanosleep(40);
    }
    __syncthreads();
    int boff = __ldcg(&d_off[bid]);
    if (i < NNODES) {
        int r = lexcl + boff;
        d_rowptr[i] = r;
        d_cursor[i] = r;
        d_inv[i] = 1.f / (float)(v > 0 ? v : 1);
    }
}

__global__ void k_fill(const int* __restrict__ src,
                       const int* __restrict__ efeat,
                       const int* __restrict__ dst) {
    int e = blockIdx.x * blockDim.x + threadIdx.x;
    if (e >= NEDGES) return;
    int p = atomicAdd(&d_cursor[dst[e]], 1);
    d_edge[p] = ((unsigned)src[e] << 8) | (unsigned)efeat[e];
}

// ---------------- per-layer kernels ----------------
// warp per node, lane covers 2 channels (float2). 4x-unrolled edge loop with
// byte-offset packed edges. __launch_bounds__(256, 8) pins regs to 32 so all
// 8 blocks fit per SM (measured occupancy sweet spot).
__global__ void __launch_bounds__(256, 8) k_msg(const float* __restrict__ bond) {
    __shared__ __align__(16) float bsh[5 * EMBED];
    int tid = threadIdx.x;
    for (int i = tid; i < 5 * EMBED; i += 256) bsh[i] = bond[i];
    __syncthreads();
    int warp = tid >> 5, lane = tid & 31;
    int node = blockIdx.x * 8 + warp;
    if (node >= NNODES) return;
    int rs = d_rowptr[node], re = d_rowptr[node + 1];
    const char* hb = (const char*)d_h + lane * 8;
    const char* bb = (const char*)bsh + lane * 8;
    float2 a0 = make_float2(0.f, 0.f), a1 = a0, a2 = a0, a3 = a0;
    int e = rs;
    for (; e + 3 < re; e += 4) {
        unsigned p0 = d_edge[e],     p1 = d_edge[e + 1];
        unsigned p2 = d_edge[e + 2], p3 = d_edge[e + 3];
        float2 h0 = *(const float2*)(hb + (p0 & 0xFFFFFF00u));
        float2 h1 = *(const float2*)(hb + (p1 & 0xFFFFFF00u));
        float2 h2 = *(const float2*)(hb + (p2 & 0xFFFFFF00u));
        float2 h3 = *(const float2*)(hb + (p3 & 0xFFFFFF00u));
        float2 b0 = *(const float2*)(bb + ((p0 & 255u) << 8));
        float2 b1 = *(const float2*)(bb + ((p1 & 255u) << 8));
        float2 b2 = *(const float2*)(bb + ((p2 & 255u) << 8));
        float2 b3 = *(const float2*)(bb + ((p3 & 255u) << 8));
        a0.x += fmaxf(b0.x + h0.x, 0.f);  a0.y += fmaxf(b0.y + h0.y, 0.f);
        a1.x += fmaxf(b1.x + h1.x, 0.f);  a1.y += fmaxf(b1.y + h1.y, 0.f);
        a2.x += fmaxf(b2.x + h2.x, 0.f);  a2.y += fmaxf(b2.y + h2.y, 0.f);
        a3.x += fmaxf(b3.x + h3.x, 0.f);  a3.y += fmaxf(b3.y + h3.y, 0.f);
    }
    for (; e < re; e++) {
        unsigned p0 = d_edge[e];
        float2 h0 = *(const float2*)(hb + (p0 & 0xFFFFFF00u));
        float2 b0 = *(const float2*)(bb + ((p0 & 255u) << 8));
        a0.x += fmaxf(b0.x + h0.x, 0.f);  a0.y += fmaxf(b0.y + h0.y, 0.f);
    }
    a0.x += a1.x + a2.x + a3.x;
    a0.y += a1.y + a2.y + a3.y;
    float inv = d_inv[node];
    float2 hn = ((const float2*)(d_h + (size_t)node * EMBED))[lane];
    float2 o;
    o.x = a0.x * inv + hn.x;
    o.y = a0.y * inv + hn.y;
    ((float2*)(d_t + (size_t)node * EMBED))[lane] = o;
}

// GEMM with SMEM STAGING: R16's uncoalesced row accesses (32 L1 wavefronts per
// LDG/STG — ~75% of the measured L1 wall) replaced by coalesced block-level
// stage-in of t, smem compute, and coalesced stage-out of y. Two nodes per
// thread, channel-split (keeps Ws broadcast traffic halved). Stats read the
// smem-resident y (global re-read eliminated). 94KB dynamic smem.
__global__ void k_gemm(const float* __restrict__ W,
                       const float* __restrict__ b,
                       int layer) {
    extern __shared__ __align__(16) char smraw[];
    ulonglong2* Ws  = (ulonglong2*)smraw;                     // 16384 B
    float4* tbuf    = (float4*)(smraw + 16384);               // 256*17*16 B
    float4* ssum    = (float4*)(smraw + 16384 + 256 * TB_STRIDE * 16);
    float4* ssq     = ssum + 256;
    int tid = threadIdx.x;
    int base = blockIdx.x * 256;
    for (int i = tid; i < EMBED * 16; i += 256) Ws[i] = ((const ulonglong2*)W)[i];
    // coalesced stage-in of this block's 256 t-rows
    #pragma unroll 4
    for (int i = 0; i < 16; i++) {
        int idx = i * 256 + tid;
        int row = idx >> 4, c4 = idx & 15;
        if (base + row < NNODES)
            tbuf[row * TB_STRIDE + c4] = ((const float4*)d_t)[(size_t)(base + row) * 16 + c4];
    }
    __syncthreads();
    int pair = tid & 127, half = tid >> 7;
    int lr0 = pair * 2, lr1 = lr0 + 1;
    u64 accA[16], accB[16];
    {
        const u64* bp = (const u64*)b + half * 16;
        #pragma unroll
        for (int i = 0; i < 16; i++) { accA[i] = bp[i]; accB[i] = bp[i]; }
        #pragma unroll 4
        for (int k4 = 0; k4 < 16; k4++) {
            float4 ta = tbuf[lr0 * TB_STRIDE + k4];
            float4 tb = tbuf[lr1 * TB_STRIDE + k4];
            #pragma unroll
            for (int j = 0; j < 4; j++) {
                float fa = (j == 0) ? ta.x : (j == 1) ? ta.y : (j == 2) ? ta.z : ta.w;
                float fb = (j == 0) ? tb.x : (j == 1) ? tb.y : (j == 2) ? tb.z : tb.w;
                u64 ka = pack2(fa), kb = pack2(fb);
                int k = k4 * 4 + j;
                #pragma unroll
                for (int c8 = 0; c8 < 8; c8++) {
                    ulonglong2 w = Ws[k * 16 + half * 8 + c8];
                    accA[2 * c8]     = ffma2(ka, w.x, accA[2 * c8]);
                    accA[2 * c8 + 1] = ffma2(ka, w.y, accA[2 * c8 + 1]);
                    accB[2 * c8]     = ffma2(kb, w.x, accB[2 * c8]);
                    accB[2 * c8 + 1] = ffma2(kb, w.y, accB[2 * c8 + 1]);
                }
            }
        }
    }
    __syncthreads();   // all t reads complete before tbuf is overwritten with y
    #pragma unroll
    for (int i = 0; i < 8; i++) {
        *(ulonglong2*)&tbuf[lr0 * TB_STRIDE + half * 8 + i] =
            make_ulonglong2(accA[2 * i], accA[2 * i + 1]);
        *(ulonglong2*)&tbuf[lr1 * TB_STRIDE + half * 8 + i] =
            make_ulonglong2(accB[2 * i], accB[2 * i + 1]);
    }
    __syncthreads();   // y fully staged
    // coalesced stage-out of y
    #pragma unroll 4
    for (int i = 0; i < 16; i++) {
        int idx = i * 256 + tid;
        int row = idx >> 4, c4 = idx & 15;
        if (base + row < NNODES)
            ((float4*)d_y)[(size_t)(base + row) * 16 + c4] = tbuf[row * TB_STRIDE + c4];
    }
    // stats from the smem-resident y
    int c4 = tid & 15, grp = tid >> 4;
    float4 sum = make_float4(0.f, 0.f, 0.f, 0.f), sq = sum;
    for (int r = grp; r < 256; r += 16) {
        if (base + r >= NNODES) break;
        float4 v = tbuf[r * TB_STRIDE + c4];
        sum.x += v.x; sum.y += v.y; sum.z += v.z; sum.w += v.w;
        sq.x += v.x * v.x; sq.y += v.y * v.y; sq.z += v.z * v.z; sq.w += v.w * v.w;
    }
    ssum[tid] = sum; ssq[tid] = sq;
    __syncthreads();
    if (grp == 0) {
        #pragma unroll
        for (int g = 1; g < 16; g++) {
            float4 a = ssum[g * 16 + c4], q = ssq[g * 16 + c4];
            sum.x += a.x; sum.y += a.y; sum.z += a.z; sum.w += a.w;
            sq.x += q.x; sq.y += q.y; sq.z += q.z; sq.w += q.w;
        }
        float* st = d_Z.stats + layer * 128;
        atomicAdd(&st[c4 * 4 + 0], sum.x);
        atomicAdd(&st[c4 * 4 + 1], sum.y);
        atomicAdd(&st[c4 * 4 + 2], sum.z);
        atomicAdd(&st[c4 * 4 + 3], sum.w);
        atomicAdd(&st[64 + c4 * 4 + 0], sq.x);
        atomicAdd(&st[64 + c4 * 4 + 1], sq.y);
        atomicAdd(&st[64 + c4 * 4 + 2], sq.z);
        atomicAdd(&st[64 + c4 * 4 + 3], sq.w);
    }
}

// normalize + gamma/beta + relu + residual (h += act), float4 wide (layers 0,1)
__global__ void k_bn(int layer, const float* __restrict__ gamma,
                     const float* __restrict__ beta) {
    int i = blockIdx.x * blockDim.x + threadIdx.x;   // float4 index
    if (i >= NNODES * 16) return;
    int c4 = i & 15;
    const float* st = d_Z.stats + layer * 128;
    const float invN = 1.f / (float)NNODES;
    float4 s1 = ((const float4*)st)[c4];
    float4 s2 = ((const float4*)(st + 64))[c4];
    float4 g  = ((const float4*)gamma)[c4];
    float4 be = ((const float4*)beta)[c4];
    float4 y  = ((const float4*)d_y)[i];
    float4 h  = ((const float4*)d_h)[i];
    float mu, var, rs, v;
    #define BN1(X) \
        mu = s1.X * invN; var = s2.X * invN - mu * mu; \
        rs = rsqrtf(fmaxf(var, 0.f) + BN_EPS); \
        v = fmaxf((y.X - mu) * rs * g.X + be.X, 0.f); \
        h.X += v;
    BN1(x) BN1(y) BN1(z) BN1(w)
    #undef BN1
    ((float4*)d_h)[i] = h;
}

// ---------------- tail: last-layer bn folded into pool + pred ----------------
__global__ void k_poolpred(const int* __restrict__ gids,
                           const float* __restrict__ gamma,
                           const float* __restrict__ beta,
                           const float* __restrict__ W,
                           const float* __restrict__ b,
                           float* __restrict__ out) {
    __shared__ float red[256];
    __shared__ float gs[EMBED];
    __shared__ int range[2];
    int g = blockIdx.x, tid = threadIdx.x;
    int c = tid & 63, grp = tid >> 6;
    if (tid < 2) {
        int target = g + tid;
        int lo = 0, hi = NNODES;
        while (lo < hi) { int m = (lo + hi) >> 1; if (gids[m] < target) lo = m + 1; else hi = m; }
        range[tid] = lo;
    }
    // per-channel BN constants for last layer
    const float invN = 1.f / (float)NNODES;
    const float* st = d_Z.stats + (NCONV - 1) * 128;
    float mu = st[c] * invN;
    float var = st[64 + c] * invN - mu * mu;
    float rsg = rsqrtf(fmaxf(var, 0.f) + BN_EPS) * gamma[c];
    float be = beta[c];
    __syncthreads();
    int start = range[0], end = range[1];
    float acc = 0.f;
    for (int n = start + grp; n < end; n += 4) {
        float hv = d_h[(size_t)n * EMBED + c];
        float yv = d_y[(size_t)n * EMBED + c];
        acc += hv + (yv - mu) * rsg + be;
    }
    red[tid] = acc;
    __syncthreads();
    if (grp == 0) {
        float s = red[c] + red[64 + c] + red[128 + c] + red[192 + c];
        int cntg = end - start;
        gs[c] = s / (float)(cntg > 0 ? cntg : 1);
    }
    __syncthreads();
    if (tid < OUTDIM) {
        float a = b[tid];
        #pragma unroll
        for (int k = 0; k < EMBED; k++) a += gs[k] * W[k * OUTDIM + tid];
        out[g * OUTDIM + tid] = a;
    }
}

// ---------------- launch ----------------
extern "C" void kernel_launch(void* const* d_in, const int* in_sizes, int n_in,
                              void* d_out, int out_size) {
    const int*   nfeat      = (const int*)d_in[0];
    const int*   efeat      = (const int*)d_in[1];
    const int*   src        = (const int*)d_in[2];
    const int*   dst        = (const int*)d_in[3];
    const int*   gids       = (const int*)d_in[4];
    const float* atom_embed = (const float*)d_in[5];
    const float* bond_embed = (const float*)d_in[6];
    const float* conv_W     = (const float*)d_in[7];
    const float* conv_b     = (const float*)d_in[8];
    const float* bn_gamma   = (const float*)d_in[9];
    const float* bn_beta    = (const float*)d_in[10];
    const float* pred_W     = (const float*)d_in[11];
    const float* pred_b     = (const float*)d_in[12];
    float* out = (float*)d_out;

    cudaFuncSetAttribute(k_gemm, cudaFuncAttributeMaxDynamicSharedMemorySize,
                         GEMM_SMEM);

    void* zp = nullptr;
    cudaGetSymbolAddress(&zp, d_Z);
    cudaMemsetAsync(zp, 0, sizeof(ZBuf), 0);

    k_setup<<<SCAN_BLOCKS, 256>>>(nfeat, (const float4*)atom_embed, dst);
    k_fill<<<(NEDGES + 255) / 256, 256>>>(src, efeat, dst);

    for (int i = 0; i < NCONV; i++) {
        k_msg<<<(NNODES + 7) / 8, 256>>>(bond_embed + i * 5 * EMBED);
        k_gemm<<<SCAN_BLOCKS, 256, GEMM_SMEM>>>(conv_W + i * EMBED * EMBED,
                                                conv_b + i * EMBED, i);
        if (i < NCONV - 1)
            k_bn<<<(NNODES * 16 + 255) / 256, 256>>>(i, bn_gamma + i * EMBED,
                                                     bn_beta + i * EMBED);
    }

    k_poolpred<<<NGRAPHS, 256>>>(gids, bn_gamma + (NCONV - 1) * EMBED,
                                 bn_beta + (NCONV - 1) * EMBED,
                                 pred_W, pred_b, out);
}